// round 13
// baseline (speedup 1.0000x reference)
#include <cuda_runtime.h>
#include <cuda_fp16.h>

// out[b,o] = max_k min(x[b,k], w[k,o])  (STE forward == hard max-min)
// x: [B,512] f32 uniform[0,1), w: [512,512] f32, out f32. B = 1024.
//
// Candidate algorithm (R6 structure, measured best): per b-row, tier-1
// candidates x >= 0.875 (~64; P(out<0.875)=e^-8~3.4e-4), tier-2
// [0.78,0.875) extension for certificate failures, exact full scan as last
// resort (any-distribution correctness).
//
// R13: no packing kernel — the hot loop gathers w rows in fp32 directly
// (LDG.128 = 4 outputs/thread). R6 evidence: loop is latency-bound (L2 13%,
// dram 2%), so doubling gather bytes is free and the 2.7us packw launch
// disappears. Entire computation is now exact fp32 (certificates exact).

#define KDIM 512
#define ODIM 512
#define NT   128          // thread owns outputs [4t, 4t+4)
#define CUT1 0.875f
#define CUT2 0.78f
#define C1MAX 160         // tier1 ~64 +- 7.5 -> 12.8 sigma headroom
#define C2MAX 160         // tier2 ~49 +- 6.7

__global__ __launch_bounds__(NT)
void maxmin_kernel(const float* __restrict__ x,
                   const float* __restrict__ w,
                   float* __restrict__ out)
{
    __shared__ float xs[KDIM];
    __shared__ uint2 c1[C1MAX];       // {float bits of x, k*128 (uint4 row idx)}
    __shared__ uint2 c2[C2MAX];
    __shared__ int   s_n1, s_n2, s_ovf;

    const int b   = blockIdx.x;
    const int tid = threadIdx.x;      // owns outputs 4*tid .. 4*tid+3

    if (tid == 0) { s_n1 = 0; s_n2 = 0; s_ovf = 0; }
    // zero c1 so zero-padded batches are harmless (min(0,w)=0, w >= 0)
    c1[tid] = make_uint2(0u, 0u);
    if (tid + NT < C1MAX) c1[tid + NT] = make_uint2(0u, 0u);
    __syncthreads();

    // ---- stage x row (for fallback) + threshold selection ----
    {
        float4 v = reinterpret_cast<const float4*>(x + (size_t)b * KDIM)[tid];
        reinterpret_cast<float4*>(xs)[tid] = v;
        float e[4] = {v.x, v.y, v.z, v.w};
#pragma unroll
        for (int q = 0; q < 4; q++) {
            float xv = e[q];
            if (xv >= CUT2) {
                int k = tid * 4 + q;
                unsigned xb = *reinterpret_cast<unsigned*>(&xv);
                if (xv >= CUT1) {
                    int p = atomicAdd(&s_n1, 1);
                    if (p < C1MAX) c1[p] = make_uint2(xb, (unsigned)(k * 128));
                    else           s_ovf = 1;
                } else {
                    int p = atomicAdd(&s_n2, 1);
                    if (p < C2MAX) c2[p] = make_uint2(xb, (unsigned)(k * 128));
                    else           s_ovf = 1;
                }
            }
        }
    }
    __syncthreads();

    const int cnt1 = s_n1;
    const int cnt2 = (s_n2 < C2MAX) ? s_n2 : C2MAX;
    const int ovf  = s_ovf;
    const int n1p  = (cnt1 + 7) & ~7;       // zero-padded length, <= C1MAX

    const float4* wq = reinterpret_cast<const float4*>(w);  // row k = 128 float4

    float a0 = 0.0f, a1 = 0.0f, a2 = 0.0f, a3 = 0.0f;  // inputs >= 0

    if (!ovf) {
        for (int t = 0; t < n1p; t += 8) {  // MLP=8 LDG.128 batches
            float4   wv[8];
            float    xv[8];
#pragma unroll
            for (int u = 0; u < 8; u++) {
                uint2 c = c1[t + u];        // broadcast LDS.64
                xv[u] = __uint_as_float(c.x);
                wv[u] = wq[c.y + tid];      // LDG.128
            }
#pragma unroll
            for (int u = 0; u < 8; u++) {
                a0 = fmaxf(a0, fminf(xv[u], wv[u].x));
                a1 = fmaxf(a1, fminf(xv[u], wv[u].y));
                a2 = fmaxf(a2, fminf(xv[u], wv[u].z));
                a3 = fmaxf(a3, fminf(xv[u], wv[u].w));
            }
        }
    }

    // ---- tier-2 extension (exact certificate: excluded k have min < CUT1) ----
    if (!ovf && (a0 < CUT1 || a1 < CUT1 || a2 < CUT1 || a3 < CUT1)) {
#pragma unroll 1
        for (int t = 0; t < cnt2; t++) {
            uint2 c = c2[t];
            float4 wv = wq[c.y + tid];
            float  xv = __uint_as_float(c.x);
            a0 = fmaxf(a0, fminf(xv, wv.x));
            a1 = fmaxf(a1, fminf(xv, wv.y));
            a2 = fmaxf(a2, fminf(xv, wv.z));
            a3 = fmaxf(a3, fminf(xv, wv.w));
        }
    }

    float r[4] = {a0, a1, a2, a3};

    // ---- exact full-scan fallback (P ~ e^-25 per output for uniform) ----
#pragma unroll 1
    for (int j = 0; j < 4; j++) {
        if (ovf || r[j] < CUT2) {
            int o = tid * 4 + j;
            float v = 0.0f;
#pragma unroll 1
            for (int k = 0; k < KDIM; k += 4) {
                float m0 = fminf(xs[k],     w[(size_t)(k)     * ODIM + o]);
                float m1 = fminf(xs[k + 1], w[(size_t)(k + 1) * ODIM + o]);
                float m2 = fminf(xs[k + 2], w[(size_t)(k + 2) * ODIM + o]);
                float m3 = fminf(xs[k + 3], w[(size_t)(k + 3) * ODIM + o]);
                v = fmaxf(v, fmaxf(fmaxf(m0, m1), fmaxf(m2, m3)));
            }
            r[j] = v;
        }
    }

    reinterpret_cast<float4*>(out + (size_t)b * ODIM)[tid] =
        make_float4(r[0], r[1], r[2], r[3]);
}

extern "C" void kernel_launch(void* const* d_in, const int* in_sizes, int n_in,
                              void* d_out, int out_size)
{
    const float* x = (const float*)d_in[0];   // [B, 512]
    const float* w = (const float*)d_in[1];   // [512, 512]
    float* out = (float*)d_out;

    int B = in_sizes[0] / KDIM;               // 1024

    maxmin_kernel<<<B, NT>>>(x, w, out);
}